// round 15
// baseline (speedup 1.0000x reference)
#include <cuda_runtime.h>
#include <cuda_fp16.h>
#include <cstdint>

#define NF     65536
#define TSCAN  65535
#define CHUNK  32
#define NCH    2048

// ===========================================================================
// Device scratch (no runtime allocation allowed)
// ===========================================================================
__device__ __align__(16) __half2 g_ab[(size_t)NF * 128];   // (a,b) per (f,j)  32 MiB
__device__ __align__(16) float2  g_comp [NCH * 128];
__device__ __align__(16) float   g_carry[NCH * 128];
__device__ __align__(16) __half  g_w1p[8 * 256 * 64];      // chunked, row-permuted
__device__ __align__(16) __half  g_w2p[256 * 128];

// ===========================================================================
// Helpers
// ===========================================================================
__device__ __forceinline__ uint32_t smem_u32(const void* p) {
    uint32_t a;
    asm("{ .reg .u64 t; cvta.to.shared.u64 t, %1; cvt.u32.u64 %0, t; }" : "=r"(a) : "l"(p));
    return a;
}
__device__ __forceinline__ void cpa16(uint32_t s, const void* g) {
    asm volatile("cp.async.cg.shared.global [%0], [%1], 16;"
                 :: "r"(s), "l"(__cvta_generic_to_global(g)));
}
#define CPA_COMMIT()  asm volatile("cp.async.commit_group;" ::: "memory")
#define CPA_WAIT(n)   asm volatile("cp.async.wait_group %0;" :: "n"(n) : "memory")

__device__ __forceinline__ void mma16816(float* c, const uint32_t* a, const uint32_t* b) {
    asm volatile(
        "mma.sync.aligned.m16n8k16.row.col.f32.f16.f16.f32 "
        "{%0,%1,%2,%3}, {%4,%5,%6,%7}, {%8,%9}, {%0,%1,%2,%3};"
        : "+f"(c[0]), "+f"(c[1]), "+f"(c[2]), "+f"(c[3])
        : "r"(a[0]), "r"(a[1]), "r"(a[2]), "r"(a[3]), "r"(b[0]), "r"(b[1]));
}
__device__ __forceinline__ void ldm4(uint32_t* r, uint32_t saddr) {
    asm volatile("ldmatrix.sync.aligned.m8n8.x4.shared.b16 {%0,%1,%2,%3}, [%4];"
                 : "=r"(r[0]), "=r"(r[1]), "=r"(r[2]), "=r"(r[3]) : "r"(saddr));
}
__device__ __forceinline__ uint32_t pack_h2(__half a, __half b) {
    __half2 h = __halves2half2(a, b);
    return *(uint32_t*)&h;
}
__device__ __forceinline__ int perm_n(int n) {   // interleave j / j+128
    return (n & 1) ? 128 + (n >> 1) : (n >> 1);
}
__device__ __forceinline__ float sigm(float x) { return 1.f / (1.f + __expf(-x)); }

// ===========================================================================
// Prep: W1 -> fp16, rows permuted, chunked [8c][256n'][64k];  W2 -> fp16
// ===========================================================================
__global__ void k_prep_w1(const float* __restrict__ W1)
{
    int idx = blockIdx.x * 256 + threadIdx.x;
    if (idx >= 256 * 512) return;
    int np = idx >> 9, k = idx & 511;
    float v = W1[perm_n(np) * 512 + k];
    g_w1p[(k >> 6) * 16384 + np * 64 + (k & 63)] = __float2half_rn(v);
}
__global__ void k_prep_w2(const float* __restrict__ W2)
{
    int idx = blockIdx.x * 256 + threadIdx.x;
    if (idx >= 256 * 128) return;
    g_w2p[idx] = __float2half_rn(W2[idx]);
}

// ===========================================================================
// GEMM1: D[f 128][n' 256] = x^T * W1p^T (fp16 product, f32 accum)
// 512 threads, warps = 4(f) x 4(n). ldmatrix fragment loads.
// smem: stage f32 [2][64][132] | xh [2][128][72] | W [2][256][72] | B1
// ===========================================================================
#define SM1_STAGE 0
#define SM1_XH    67584
#define SM1_W     104448
#define SM1_B1    178176
#define SM1_SIZE  179200

__global__ void __launch_bounds__(512)
k_gemm1(const float* __restrict__ inp, const float* __restrict__ B1)
{
    extern __shared__ char smem[];
    const uint32_t sb = smem_u32(smem);
    const int tid = threadIdx.x, lane = tid & 31, wid = tid >> 5;
    const int g = lane >> 2, t = lane & 3;
    const int fw = (wid & 3) * 32, nw = (wid >> 2) * 64;
    const int f0 = blockIdx.x * 128;

    // ldmatrix lane geometry
    const int a_row = (lane & 15), a_koff = (lane >> 4) << 3;             // A
    const int b_row = (lane & 7) + ((lane >> 4) << 3);                    // B
    const int b_koff = ((lane >> 3) & 1) << 3;

    if (tid < 256) ((float*)(smem + SM1_B1))[tid] = B1[perm_n(tid)];

    float acc[2][8][4];
    #pragma unroll
    for (int a = 0; a < 2; a++)
        #pragma unroll
        for (int b = 0; b < 8; b++)
            #pragma unroll
            for (int q = 0; q < 4; q++) acc[a][b][q] = 0.f;

    auto load_chunk = [&](int c, int buf) {
        const char* xg = (const char*)inp + ((size_t)(c * 64) * NF + f0) * 4;
        #pragma unroll
        for (int i = tid; i < 2048; i += 512)
            cpa16(sb + SM1_STAGE + buf * 33792 + (i >> 5) * 528 + (i & 31) * 16,
                  xg + (size_t)(i >> 5) * (NF * 4) + (i & 31) * 16);
        const char* wg = (const char*)g_w1p + (size_t)c * 32768;
        #pragma unroll
        for (int i = tid; i < 2048; i += 512)
            cpa16(sb + SM1_W + buf * 36864 + (i >> 3) * 144 + (i & 7) * 16,
                  wg + i * 16);
    };

    load_chunk(0, 0);
    CPA_COMMIT();

    const int fcv = tid & 127, kg = tid >> 7;     // convert-pass assignment

    for (int c = 0; c < 8; c++) {
        const int buf = c & 1;
        CPA_WAIT(0);
        __syncthreads();                           // x(c)+W(c) ready; old bufs free

        if (c < 7) { load_chunk(c + 1, buf ^ 1); CPA_COMMIT(); }

        {   // convert stage -> fp16 plane (each element exactly once)
            const float* st = (const float*)(smem + SM1_STAGE + buf * 33792);
            __half* xh = (__half*)(smem + SM1_XH + buf * 18432);
            #pragma unroll
            for (int kk = 0; kk < 16; kk += 2) {
                int k = kg * 16 + kk;
                float v0 = st[k * 132 + fcv];
                float v1 = st[(k + 1) * 132 + fcv];
                *(uint32_t*)(xh + fcv * 72 + k) =
                    pack_h2(__float2half_rn(v0), __float2half_rn(v1));
            }
        }
        __syncthreads();                           // plane ready

        const uint32_t xb = sb + SM1_XH + buf * 18432;
        const uint32_t wb = sb + SM1_W + buf * 36864;

        #pragma unroll
        for (int ks = 0; ks < 4; ks++) {
            uint32_t aa[2][4];
            #pragma unroll
            for (int mt = 0; mt < 2; mt++)
                ldm4(aa[mt], xb + ((fw + mt * 16 + a_row) * 72 + ks * 16 + a_koff) * 2);
            uint32_t bb[8][2];
            #pragma unroll
            for (int p = 0; p < 4; p++) {
                uint32_t r[4];
                ldm4(r, wb + ((nw + p * 16 + b_row) * 72 + ks * 16 + b_koff) * 2);
                bb[2*p][0] = r[0]; bb[2*p][1] = r[1];
                bb[2*p+1][0] = r[2]; bb[2*p+1][1] = r[3];
            }
            #pragma unroll
            for (int mt = 0; mt < 2; mt++)
                #pragma unroll
                for (int nt = 0; nt < 8; nt++)
                    mma16816(acc[mt][nt], aa[mt], bb[nt]);
        }
    }

    // Epilogue: sigmoid+gate -> stage (a,b) half2 in smem.
    __syncthreads();
    const float* sB1 = (const float*)(smem + SM1_B1);
    __half2* sAB = (__half2*)smem;                 // [128 f][pitch 132]
    #pragma unroll
    for (int mt = 0; mt < 2; mt++)
        #pragma unroll
        for (int nt = 0; nt < 8; nt++) {
            int fl = fw + mt * 16 + g;
            int nl = nw + nt * 8 + 2 * t;
            int j  = nl >> 1;
            float b0 = sB1[nl], b1 = sB1[nl + 1];
            const float* cc = acc[mt][nt];
            float h0 = sigm(cc[0] + b0), h1 = sigm(cc[1] + b1);
            sAB[fl * 132 + j] = __floats2half2_rn(h0 * h1, 1.f - h0);
            h0 = sigm(cc[2] + b0); h1 = sigm(cc[3] + b1);
            sAB[(fl + 8) * 132 + j] = __floats2half2_rn(h0 * h1, 1.f - h0);
        }
    __syncthreads();

    // Coalesced copy to g_ab
    const float4* s4 = (const float4*)smem;
    float4* g4 = (float4*)(g_ab + (size_t)f0 * 128);
    #pragma unroll
    for (int i = tid; i < 4096; i += 512)
        g4[i] = s4[(i >> 5) * 33 + (i & 31)];

    // Fused chunk composites: 4 chunks x 128 lanes = 512 threads
    {
        const int c = tid >> 7, j = tid & 127;
        float A = 1.f, B = 0.f;
        #pragma unroll 8
        for (int tt = 0; tt < 32; tt++) {
            float2 v = __half22float2(sAB[(c * 32 + tt) * 132 + j]);
            B = fmaf(v.x, B, v.y);
            A *= v.x;
        }
        g_comp[(blockIdx.x * 4 + c) * 128 + j] = make_float2(A, B);
    }
}

// ===========================================================================
// Carry scan: state entering each chunk (exclusive). Shuffle-based 3-level.
// ===========================================================================
__global__ void __launch_bounds__(1024) k_scan_carry()
{
    __shared__ float wA[32], wB[32];
    const int j = blockIdx.x, c = threadIdx.x;
    const int lane = c & 31, wid = c >> 5;

    float2 v0 = g_comp[(2 * c)     * 128 + j];
    float2 v1 = g_comp[(2 * c + 1) * 128 + j];
    float A = v1.x * v0.x;
    float B = fmaf(v1.x, v0.y, v1.y);

    #pragma unroll
    for (int d = 1; d < 32; d <<= 1) {
        float Ap = __shfl_up_sync(0xffffffffu, A, d);
        float Bp = __shfl_up_sync(0xffffffffu, B, d);
        if (lane >= d) { B = fmaf(A, Bp, B); A *= Ap; }
    }
    if (lane == 31) { wA[wid] = A; wB[wid] = B; }
    __syncthreads();
    if (wid == 0) {
        float a = wA[lane], b = wB[lane];
        #pragma unroll
        for (int d = 1; d < 32; d <<= 1) {
            float ap = __shfl_up_sync(0xffffffffu, a, d);
            float bp = __shfl_up_sync(0xffffffffu, b, d);
            if (lane >= d) { b = fmaf(a, bp, b); a *= ap; }
        }
        wA[lane] = a; wB[lane] = b;
    }
    __syncthreads();

    float PB = (wid == 0) ? 0.f : wB[wid - 1];
    float eA = __shfl_up_sync(0xffffffffu, A, 1);
    float eB = __shfl_up_sync(0xffffffffu, B, 1);
    if (lane == 0) { eA = 1.f; eB = 0.f; }
    float Bex = fmaf(eA, PB, eB);

    g_carry[(2 * c)     * 128 + j] = Bex;
    g_carry[(2 * c + 1) * 128 + j] = fmaf(v0.x, Bex, v0.y);
}

// ===========================================================================
// GEMM2 (fused apply): scan-apply from global ab; ldmatrix fragments;
// epilogue staged through smem (coalesced out stores).
// smem: z [128][136] f16 | W2 [256][136] f16 | B2 f32 ; post-MMA reuse as
//       sOut [128][132] f32 (two n-halves).
// ===========================================================================
#define SM2_Z    0
#define SM2_W    34816
#define SM2_B2   104448
#define SM2_SIZE 105472

__global__ void __launch_bounds__(512)
k_gemm2(const float* __restrict__ B2, float* __restrict__ out)
{
    extern __shared__ char smem[];
    const uint32_t sb = smem_u32(smem);
    const int tid = threadIdx.x, lane = tid & 31, wid = tid >> 5;
    const int g = lane >> 2, t = lane & 3;
    const int fw = (wid & 3) * 32, nw = (wid >> 2) * 64;
    const int f0 = blockIdx.x * 128;

    const int a_row = (lane & 15), a_koff = (lane >> 4) << 3;
    const int b_row = (lane & 7) + ((lane >> 4) << 3);
    const int b_koff = ((lane >> 3) & 1) << 3;

    if (tid < 256) ((float*)(smem + SM2_B2))[tid] = B2[tid];

    {   // W2 load overlaps the scan-apply below
        const char* wg = (const char*)g_w2p;
        #pragma unroll
        for (int i = tid; i < 4096; i += 512)
            cpa16(sb + SM2_W + (i >> 4) * 272 + (i & 15) * 16, wg + i * 16);
        CPA_COMMIT();
    }

    // Fused scan-apply from GLOBAL ab: thread (c = tid>>7, j = tid&127)
    {
        const int c = tid >> 7, j = tid & 127;
        const __half2* abp = g_ab + (size_t)(f0 + c * 32) * 128 + j;
        __half* zs = (__half*)(smem + SM2_Z);
        float s = g_carry[(blockIdx.x * 4 + c) * 128 + j];
        zs[(c * 32) * 136 + j] = __float2half_rn(s);
        #pragma unroll
        for (int tt = 0; tt < 31; tt++) {
            float2 v = __half22float2(abp[(size_t)tt * 128]);
            s = fmaf(v.x, s, v.y);
            zs[(c * 32 + tt + 1) * 136 + j] = __float2half_rn(s);
        }
    }
    CPA_WAIT(0);
    __syncthreads();

    float acc[2][8][4];
    #pragma unroll
    for (int a = 0; a < 2; a++)
        #pragma unroll
        for (int b = 0; b < 8; b++)
            #pragma unroll
            for (int q = 0; q < 4; q++) acc[a][b][q] = 0.f;

    #pragma unroll
    for (int ks = 0; ks < 8; ks++) {
        uint32_t aa[2][4];
        #pragma unroll
        for (int mt = 0; mt < 2; mt++)
            ldm4(aa[mt], sb + SM2_Z + ((fw + mt * 16 + a_row) * 136 + ks * 16 + a_koff) * 2);
        uint32_t bb[8][2];
        #pragma unroll
        for (int p = 0; p < 4; p++) {
            uint32_t r[4];
            ldm4(r, sb + SM2_W + ((nw + p * 16 + b_row) * 136 + ks * 16 + b_koff) * 2);
            bb[2*p][0] = r[0]; bb[2*p][1] = r[1];
            bb[2*p+1][0] = r[2]; bb[2*p+1][1] = r[3];
        }
        #pragma unroll
        for (int mt = 0; mt < 2; mt++)
            #pragma unroll
            for (int nt = 0; nt < 8; nt++)
                mma16816(acc[mt][nt], aa[mt], bb[nt]);
    }

    // Epilogue: two passes of 128 n-rows, staged in smem for coalesced stores.
    const float* sB2 = (const float*)(smem + SM2_B2);
    float* sOut = (float*)smem;                    // [128 n][pitch 132] f32
    #pragma unroll
    for (int h = 0; h < 2; h++) {
        __syncthreads();
        if ((wid >> 3) == h) {
            #pragma unroll
            for (int mt = 0; mt < 2; mt++)
                #pragma unroll
                for (int nt = 0; nt < 8; nt++) {
                    int fl  = fw + mt * 16 + g;
                    int nl  = nw + nt * 8 + 2 * t;
                    int nlh = nl - h * 128;
                    const float* cc = acc[mt][nt];
                    float b0 = sB2[nl], b1 = sB2[nl + 1];
                    sOut[nlh * 132 + fl]           = 1.f / (1.f + __expf(cc[0] + b0));
                    sOut[(nlh + 1) * 132 + fl]     = 1.f / (1.f + __expf(cc[1] + b1));
                    sOut[nlh * 132 + fl + 8]       = 1.f / (1.f + __expf(cc[2] + b0));
                    sOut[(nlh + 1) * 132 + fl + 8] = 1.f / (1.f + __expf(cc[3] + b1));
                }
        }
        __syncthreads();
        #pragma unroll
        for (int i = tid; i < 4096; i += 512) {
            int r = i >> 5, q = i & 31;
            ((float4*)(out + (size_t)(h * 128 + r) * NF + f0))[q] =
                ((const float4*)(sOut + r * 132))[q];
        }
    }
}

// ===========================================================================
extern "C" void kernel_launch(void* const* d_in, const int* in_sizes, int n_in,
                              void* d_out, int out_size)
{
    const float* inp = (const float*)d_in[0];   // (512, 65536)
    const float* W1  = (const float*)d_in[1];   // (256, 512)
    const float* B1  = (const float*)d_in[2];   // (256, 1)
    const float* W2  = (const float*)d_in[3];   // (256, 128)
    const float* B2  = (const float*)d_in[4];   // (256, 1)
    float* out = (float*)d_out;                 // (256, 65536)

    cudaFuncSetAttribute(k_gemm1, cudaFuncAttributeMaxDynamicSharedMemorySize, SM1_SIZE);
    cudaFuncSetAttribute(k_gemm2, cudaFuncAttributeMaxDynamicSharedMemorySize, SM2_SIZE);

    k_prep_w1<<<512, 256>>>(W1);
    k_prep_w2<<<128, 256>>>(W2);
    k_gemm1<<<NF / 128, 512, SM1_SIZE>>>(inp, B1);
    k_scan_carry<<<128, 1024>>>();
    k_gemm2<<<NF / 128, 512, SM2_SIZE>>>(B2, out);
}

// round 17
// speedup vs baseline: 1.1515x; 1.1515x over previous
#include <cuda_runtime.h>
#include <cuda_fp16.h>
#include <cstdint>

#define NF     65536
#define TSCAN  65535
#define CHUNK  32
#define NCH    2048

// ===========================================================================
// Device scratch (no runtime allocation allowed)
// ===========================================================================
__device__ __align__(16) __half2 g_ab[(size_t)NF * 128];   // (a,b) per (f,j)  32 MiB
__device__ __align__(16) float2  g_comp [NCH * 128];
__device__ __align__(16) float   g_carry[NCH * 128];
__device__ __align__(16) __half  g_w1p[8 * 256 * 64];      // chunked, row-permuted
__device__ __align__(16) __half  g_w2p[256 * 128];

// ===========================================================================
// Helpers
// ===========================================================================
__device__ __forceinline__ uint32_t smem_u32(const void* p) {
    uint32_t a;
    asm("{ .reg .u64 t; cvta.to.shared.u64 t, %1; cvt.u32.u64 %0, t; }" : "=r"(a) : "l"(p));
    return a;
}
__device__ __forceinline__ void cpa16(uint32_t s, const void* g) {
    asm volatile("cp.async.cg.shared.global [%0], [%1], 16;"
                 :: "r"(s), "l"(__cvta_generic_to_global(g)));
}
#define CPA_COMMIT()  asm volatile("cp.async.commit_group;" ::: "memory")
#define CPA_WAIT(n)   asm volatile("cp.async.wait_group %0;" :: "n"(n) : "memory")

__device__ __forceinline__ void mma16816(float* c, const uint32_t* a, const uint32_t* b) {
    asm volatile(
        "mma.sync.aligned.m16n8k16.row.col.f32.f16.f16.f32 "
        "{%0,%1,%2,%3}, {%4,%5,%6,%7}, {%8,%9}, {%0,%1,%2,%3};"
        : "+f"(c[0]), "+f"(c[1]), "+f"(c[2]), "+f"(c[3])
        : "r"(a[0]), "r"(a[1]), "r"(a[2]), "r"(a[3]), "r"(b[0]), "r"(b[1]));
}
__device__ __forceinline__ uint32_t pack_h2(__half a, __half b) {
    __half2 h = __halves2half2(a, b);
    return *(uint32_t*)&h;
}
__device__ __forceinline__ int perm_n(int n) {   // interleave j / j+128
    return (n & 1) ? 128 + (n >> 1) : (n >> 1);
}
__device__ __forceinline__ float sigm(float x) { return 1.f / (1.f + __expf(-x)); }

// ===========================================================================
// Prep (merged): W1 -> fp16 permuted chunks; W2 -> fp16
// ===========================================================================
__global__ void k_prep(const float* __restrict__ W1, const float* __restrict__ W2)
{
    if (blockIdx.x < 512) {
        int idx = blockIdx.x * 256 + threadIdx.x;
        int np = idx >> 9, k = idx & 511;
        float v = W1[perm_n(np) * 512 + k];
        g_w1p[(k >> 6) * 16384 + np * 64 + (k & 63)] = __float2half_rn(v);
    } else {
        int idx = (blockIdx.x - 512) * 256 + threadIdx.x;
        g_w2p[idx] = __float2half_rn(W2[idx]);
    }
}

// ===========================================================================
// GEMM1: D[f 64][n' 256] = x^T * W1p^T (fp16 product, f32 accum)
// 512 threads, warps = 4(f:16 rows) x 4(n:64), 2 CTAs/SM.
// smem: stage f32 [64k][68f] | xh [2][64f][72k] f16 | W [2][256][72] f16 | B1
// ===========================================================================
#define SM1_STAGE 0
#define SM1_XH    17408
#define SM1_W     35840
#define SM1_B1    109568
#define SM1_SIZE  110592

__global__ void __launch_bounds__(512, 2)
k_gemm1(const float* __restrict__ inp, const float* __restrict__ B1)
{
    extern __shared__ char smem[];
    const uint32_t sb = smem_u32(smem);
    const int tid = threadIdx.x, lane = tid & 31, wid = tid >> 5;
    const int g = lane >> 2, t = lane & 3;
    const int fw = (wid & 3) * 16, nw = (wid >> 2) * 64;
    const int f0 = blockIdx.x * 64;

    if (tid < 256) ((float*)(smem + SM1_B1))[tid] = B1[perm_n(tid)];

    float acc[8][4];
    #pragma unroll
    for (int b = 0; b < 8; b++)
        #pragma unroll
        for (int q = 0; q < 4; q++) acc[b][q] = 0.f;

    auto load_chunk = [&](int c, int wbuf) {
        const char* xg = (const char*)inp + ((size_t)(c * 64) * NF + f0) * 4;
        #pragma unroll
        for (int i = tid; i < 1024; i += 512)
            cpa16(sb + SM1_STAGE + (i >> 4) * 272 + (i & 15) * 16,
                  xg + (size_t)(i >> 4) * (NF * 4) + (i & 15) * 16);
        const char* wg = (const char*)g_w1p + (size_t)c * 32768;
        #pragma unroll
        for (int i = tid; i < 2048; i += 512)
            cpa16(sb + SM1_W + wbuf * 36864 + (i >> 3) * 144 + (i & 7) * 16,
                  wg + i * 16);
    };

    load_chunk(0, 0);
    CPA_COMMIT();

    const int fcv = tid & 63, kg = tid >> 6;      // convert: 8 k's per thread

    for (int c = 0; c < 8; c++) {
        const int buf = c & 1;
        CPA_WAIT(0);
        __syncthreads();                           // stage(c) + W(c) ready

        {   // convert stage -> fp16 plane (each element exactly once)
            const float* st = (const float*)(smem + SM1_STAGE);
            __half* xh = (__half*)(smem + SM1_XH + buf * 9216);
            #pragma unroll
            for (int kk = 0; kk < 8; kk += 2) {
                int k = kg * 8 + kk;
                float v0 = st[k * 68 + fcv];
                float v1 = st[(k + 1) * 68 + fcv];
                *(uint32_t*)(xh + fcv * 72 + k) =
                    pack_h2(__float2half_rn(v0), __float2half_rn(v1));
            }
        }
        __syncthreads();                           // plane ready; stage free

        if (c < 7) { load_chunk(c + 1, buf ^ 1); CPA_COMMIT(); }

        const __half* xh = (const __half*)(smem + SM1_XH + buf * 9216);
        const __half* ws = (const __half*)(smem + SM1_W + buf * 36864);

        #pragma unroll
        for (int ks = 0; ks < 4; ks++) {
            uint32_t aa[4];
            #pragma unroll
            for (int r = 0; r < 4; r++) {
                int row = fw + g + ((r & 1) << 3);
                int kc  = ks * 16 + 2 * t + ((r >> 1) << 3);
                aa[r] = *(const uint32_t*)(xh + row * 72 + kc);
            }
            uint32_t bb[8][2];
            #pragma unroll
            for (int nt = 0; nt < 8; nt++) {
                const __half* wp = ws + (nw + nt * 8 + g) * 72 + ks * 16 + 2 * t;
                bb[nt][0] = *(const uint32_t*)wp;
                bb[nt][1] = *(const uint32_t*)(wp + 8);
            }
            #pragma unroll
            for (int nt = 0; nt < 8; nt++)
                mma16816(acc[nt], aa, bb[nt]);
        }
    }

    // Epilogue: sigmoid+gate -> (a,b) half2 staged in smem (overlay stage+xh).
    __syncthreads();
    const float* sB1 = (const float*)(smem + SM1_B1);
    __half2* sAB = (__half2*)smem;                 // [64 f][pitch 132]
    #pragma unroll
    for (int nt = 0; nt < 8; nt++) {
        int fl = fw + g;
        int nl = nw + nt * 8 + 2 * t;
        int j  = nl >> 1;
        float b0 = sB1[nl], b1 = sB1[nl + 1];
        const float* cc = acc[nt];
        float h0 = sigm(cc[0] + b0), h1 = sigm(cc[1] + b1);
        sAB[fl * 132 + j] = __floats2half2_rn(h0 * h1, 1.f - h0);
        h0 = sigm(cc[2] + b0); h1 = sigm(cc[3] + b1);
        sAB[(fl + 8) * 132 + j] = __floats2half2_rn(h0 * h1, 1.f - h0);
    }
    __syncthreads();

    // Coalesced copy to g_ab (64 frames x 128 lanes = 32 KB)
    const float4* s4 = (const float4*)smem;
    float4* g4 = (float4*)(g_ab + (size_t)f0 * 128);
    #pragma unroll
    for (int i = tid; i < 2048; i += 512)
        g4[i] = s4[(i >> 5) * 33 + (i & 31)];

    // Fused chunk composites: 2 chunks x 128 lanes = 256 threads
    if (tid < 256) {
        const int c = tid >> 7, j = tid & 127;
        float A = 1.f, B = 0.f;
        #pragma unroll 8
        for (int tt = 0; tt < 32; tt++) {
            float2 v = __half22float2(sAB[(c * 32 + tt) * 132 + j]);
            B = fmaf(v.x, B, v.y);
            A *= v.x;
        }
        g_comp[(blockIdx.x * 2 + c) * 128 + j] = make_float2(A, B);
    }
}

// ===========================================================================
// Carry scan: state entering each chunk (exclusive). Shuffle-based 3-level.
// ===========================================================================
__global__ void __launch_bounds__(1024) k_scan_carry()
{
    __shared__ float wA[32], wB[32];
    const int j = blockIdx.x, c = threadIdx.x;
    const int lane = c & 31, wid = c >> 5;

    float2 v0 = g_comp[(2 * c)     * 128 + j];
    float2 v1 = g_comp[(2 * c + 1) * 128 + j];
    float A = v1.x * v0.x;
    float B = fmaf(v1.x, v0.y, v1.y);

    #pragma unroll
    for (int d = 1; d < 32; d <<= 1) {
        float Ap = __shfl_up_sync(0xffffffffu, A, d);
        float Bp = __shfl_up_sync(0xffffffffu, B, d);
        if (lane >= d) { B = fmaf(A, Bp, B); A *= Ap; }
    }
    if (lane == 31) { wA[wid] = A; wB[wid] = B; }
    __syncthreads();
    if (wid == 0) {
        float a = wA[lane], b = wB[lane];
        #pragma unroll
        for (int d = 1; d < 32; d <<= 1) {
            float ap = __shfl_up_sync(0xffffffffu, a, d);
            float bp = __shfl_up_sync(0xffffffffu, b, d);
            if (lane >= d) { b = fmaf(a, bp, b); a *= ap; }
        }
        wA[lane] = a; wB[lane] = b;
    }
    __syncthreads();

    float PB = (wid == 0) ? 0.f : wB[wid - 1];
    float eA = __shfl_up_sync(0xffffffffu, A, 1);
    float eB = __shfl_up_sync(0xffffffffu, B, 1);
    if (lane == 0) { eA = 1.f; eB = 0.f; }
    float Bex = fmaf(eA, PB, eB);

    g_carry[(2 * c)     * 128 + j] = Bex;
    g_carry[(2 * c + 1) * 128 + j] = fmaf(v0.x, Bex, v0.y);
}

// ===========================================================================
// GEMM2 (fused apply): M=64 tiles, 2 CTAs/SM. Scan-apply from global ab
// overlapped with W2 cp.async; epilogue staged via smem (4 n-quarters).
// smem: z [64][136] f16 | W2 [256][136] f16 | B2 f32 ; sOut overlays z.
// ===========================================================================
#define SM2_Z    0
#define SM2_W    17408
#define SM2_B2   87040
#define SM2_SIZE 88064

__global__ void __launch_bounds__(512, 2)
k_gemm2(const float* __restrict__ B2, float* __restrict__ out)
{
    extern __shared__ char smem[];
    const uint32_t sb = smem_u32(smem);
    const int tid = threadIdx.x, lane = tid & 31, wid = tid >> 5;
    const int g = lane >> 2, t = lane & 3;
    const int fw = (wid & 3) * 16, nw = (wid >> 2) * 64;
    const int f0 = blockIdx.x * 64;

    if (tid < 256) ((float*)(smem + SM2_B2))[tid] = B2[tid];

    {   // W2 load overlaps the scan-apply below
        const char* wg = (const char*)g_w2p;
        #pragma unroll
        for (int i = tid; i < 4096; i += 512)
            cpa16(sb + SM2_W + (i >> 4) * 272 + (i & 15) * 16, wg + i * 16);
        CPA_COMMIT();
    }

    // Fused scan-apply from GLOBAL ab: 2 chunks x 128 lanes = 256 threads
    if (tid < 256) {
        const int c = tid >> 7, j = tid & 127;
        const __half2* abp = g_ab + (size_t)(f0 + c * 32) * 128 + j;
        __half* zs = (__half*)(smem + SM2_Z);
        float s = g_carry[(blockIdx.x * 2 + c) * 128 + j];
        zs[(c * 32) * 136 + j] = __float2half_rn(s);
        #pragma unroll
        for (int tt = 0; tt < 31; tt++) {
            float2 v = __half22float2(abp[(size_t)tt * 128]);
            s = fmaf(v.x, s, v.y);
            zs[(c * 32 + tt + 1) * 136 + j] = __float2half_rn(s);
        }
    }
    CPA_WAIT(0);
    __syncthreads();

    const __half* sz = (const __half*)(smem + SM2_Z);
    const __half* sw = (const __half*)(smem + SM2_W);

    float acc[8][4];
    #pragma unroll
    for (int b = 0; b < 8; b++)
        #pragma unroll
        for (int q = 0; q < 4; q++) acc[b][q] = 0.f;

    #pragma unroll
    for (int ks = 0; ks < 8; ks++) {
        uint32_t aa[4];
        #pragma unroll
        for (int r = 0; r < 4; r++) {
            int row = fw + g + ((r & 1) << 3);
            int kc  = ks * 16 + 2 * t + ((r >> 1) << 3);
            aa[r] = *(const uint32_t*)(sz + row * 136 + kc);
        }
        uint32_t bb[8][2];
        #pragma unroll
        for (int nt = 0; nt < 8; nt++) {
            const __half* wp = sw + (nw + nt * 8 + g) * 136 + ks * 16 + 2 * t;
            bb[nt][0] = *(const uint32_t*)wp;
            bb[nt][1] = *(const uint32_t*)(wp + 8);
        }
        #pragma unroll
        for (int nt = 0; nt < 8; nt++)
            mma16816(acc[nt], aa, bb[nt]);
    }

    // Epilogue: 4 passes of 64 n-rows, staged in smem for coalesced stores.
    const float* sB2 = (const float*)(smem + SM2_B2);
    float* sOut = (float*)smem;                    // [64 n][pitch 68] f32
    #pragma unroll
    for (int h = 0; h < 4; h++) {
        __syncthreads();
        if ((wid >> 2) == h) {
            #pragma unroll
            for (int nt = 0; nt < 8; nt++) {
                int fl  = fw + g;
                int nl  = nw + nt * 8 + 2 * t;
                int nlh = nl - h * 64;
                const float* cc = acc[nt];
                float b0 = sB2[nl], b1 = sB2[nl + 1];
                sOut[nlh * 68 + fl]           = 1.f / (1.f + __expf(cc[0] + b0));
                sOut[(nlh + 1) * 68 + fl]     = 1.f / (1.f + __expf(cc[1] + b1));
                sOut[nlh * 68 + fl + 8]       = 1.f / (1.f + __expf(cc[2] + b0));
                sOut[(nlh + 1) * 68 + fl + 8] = 1.f / (1.f + __expf(cc[3] + b1));
            }
        }
        __syncthreads();
        #pragma unroll
        for (int i = tid; i < 1024; i += 512) {
            int r = i >> 4, q = i & 15;
            ((float4*)(out + (size_t)(h * 64 + r) * NF + f0))[q] =
                ((const float4*)(sOut + r * 68))[q];
        }
    }
}

// ===========================================================================
extern "C" void kernel_launch(void* const* d_in, const int* in_sizes, int n_in,
                              void* d_out, int out_size)
{
    const float* inp = (const float*)d_in[0];   // (512, 65536)
    const float* W1  = (const float*)d_in[1];   // (256, 512)
    const float* B1  = (const float*)d_in[2];   // (256, 1)
    const float* W2  = (const float*)d_in[3];   // (256, 128)
    const float* B2  = (const float*)d_in[4];   // (256, 1)
    float* out = (float*)d_out;                 // (256, 65536)

    cudaFuncSetAttribute(k_gemm1, cudaFuncAttributeMaxDynamicSharedMemorySize, SM1_SIZE);
    cudaFuncSetAttribute(k_gemm2, cudaFuncAttributeMaxDynamicSharedMemorySize, SM2_SIZE);

    k_prep<<<640, 256>>>(W1, W2);
    k_gemm1<<<NF / 64, 512, SM1_SIZE>>>(inp, B1);
    k_scan_carry<<<128, 1024>>>();
    k_gemm2<<<NF / 64, 512, SM2_SIZE>>>(B2, out);
}